// round 1
// baseline (speedup 1.0000x reference)
#include <cuda_runtime.h>
#include <math.h>

// Problem constants
#define T_STEPS 512
#define BATCH   64
#define DENC    1536
#define HID     30
#define NG      120           // 4*H gate count
#define NCOL    128           // padded column count (120 gates + xa + xb + pad)
#define MROWS   (BATCH * T_STEPS)

// Scratch (device globals: allocation-free)
__device__ float g_pre[(size_t)MROWS * NCOL];   // 16 MB: per (b,t): 120 gate pre-acts + xa + xb (biases folded)
__device__ float g_WT[DENC * NCOL];             // packed weights, [k][j] layout
__device__ float g_biasc[NCOL];

// ---------------- f32x2 packed math helpers ----------------
__device__ __forceinline__ unsigned long long pk2(float lo, float hi) {
    unsigned long long r;
    asm("mov.b64 %0, {%1,%2};" : "=l"(r) : "f"(lo), "f"(hi));
    return r;
}
__device__ __forceinline__ void upk2(unsigned long long v, float& lo, float& hi) {
    asm("mov.b64 {%0,%1}, %2;" : "=f"(lo), "=f"(hi) : "l"(v));
}
__device__ __forceinline__ unsigned long long ffma2(unsigned long long a,
                                                    unsigned long long b,
                                                    unsigned long long c) {
    unsigned long long d;
    asm("fma.rn.f32x2 %0, %1, %2, %3;" : "=l"(d) : "l"(a), "l"(b), "l"(c));
    return d;
}

// ---------------- Phase 0: pack weights ----------------
// g_WT[k][j] = Wih[j][k] (j<120) | Wa[k] (j==120) | Wb[k] (j==121) | 0
// g_biasc[j] = bih[j]+bhh[j] | ba | bb | 0
__global__ void pack_kernel(const float* __restrict__ Wih, const float* __restrict__ Wa,
                            const float* __restrict__ Wb,  const float* __restrict__ bih,
                            const float* __restrict__ bhh, const float* __restrict__ ba,
                            const float* __restrict__ bb) {
    int idx = blockIdx.x * blockDim.x + threadIdx.x;
    if (idx < DENC * NCOL) {
        int k = idx >> 7, j = idx & 127;
        float v = 0.f;
        if (j < NG)           v = Wih[j * (DENC + 1) + k];
        else if (j == NG)     v = Wa[k];
        else if (j == NG + 1) v = Wb[k];
        g_WT[idx] = v;
    }
    if (idx < NCOL) {
        float bv = 0.f;
        if (idx < NG)           bv = bih[idx] + bhh[idx];
        else if (idx == NG)     bv = ba[0];
        else if (idx == NG + 1) bv = bb[0];
        g_biasc[idx] = bv;
    }
}

// ---------------- Phase 1: GEMM  pre[m][j] = x[m,:] @ WT[:,j] + bias[j] ----------------
// BM=128, BN=128, BK=16, 256 threads, each thread computes 8x8 via f32x2 (32 FFMA2/k).
// A tile stored DUPLICATED ((a,a) pairs) so both fma2 operands load straight from SMEM.
__global__ __launch_bounds__(256) void gemm_kernel(const float* __restrict__ X) {
    __shared__ unsigned long long As2[16][128];  // 16 KB, (a,a) duplicated
    __shared__ float Bs[16][128];                // 8 KB

    const int tid = threadIdx.x;
    const int m0  = blockIdx.x * 128;
    const int tx  = tid & 15;       // 0..15 -> 8 output cols
    const int ty  = tid >> 4;       // 0..15 -> 8 output rows
    // A-load mapping: row = tid/2, 8 consecutive k per thread
    const int arow = tid >> 1;
    const int acol = (tid & 1) * 8;
    // B-load mapping: k-row = tid/16, 8 consecutive j per thread
    const int bkr = tid >> 4;
    const int bjc = (tid & 15) * 8;

    unsigned long long acc[8][4];
#pragma unroll
    for (int i = 0; i < 8; i++)
#pragma unroll
        for (int p = 0; p < 4; p++) acc[i][p] = 0ull;

    const float* Xp = X + (size_t)(m0 + arow) * DENC + acol;

    for (int k0 = 0; k0 < DENC; k0 += 16) {
        float4 va0 = *(const float4*)(Xp + k0);
        float4 va1 = *(const float4*)(Xp + k0 + 4);
        float4 vb0 = *(const float4*)(&g_WT[(k0 + bkr) * NCOL + bjc]);
        float4 vb1 = *(const float4*)(&g_WT[(k0 + bkr) * NCOL + bjc + 4]);

        As2[acol + 0][arow] = pk2(va0.x, va0.x);
        As2[acol + 1][arow] = pk2(va0.y, va0.y);
        As2[acol + 2][arow] = pk2(va0.z, va0.z);
        As2[acol + 3][arow] = pk2(va0.w, va0.w);
        As2[acol + 4][arow] = pk2(va1.x, va1.x);
        As2[acol + 5][arow] = pk2(va1.y, va1.y);
        As2[acol + 6][arow] = pk2(va1.z, va1.z);
        As2[acol + 7][arow] = pk2(va1.w, va1.w);
        *(float4*)&Bs[bkr][bjc]     = vb0;
        *(float4*)&Bs[bkr][bjc + 4] = vb1;
        __syncthreads();

#pragma unroll
        for (int kk = 0; kk < 16; kk++) {
            const ulonglong2* ap = (const ulonglong2*)&As2[kk][ty * 8];
            const ulonglong2* bp = (const ulonglong2*)&Bs[kk][tx * 8];
            ulonglong2 A0 = ap[0], A1 = ap[1], A2 = ap[2], A3 = ap[3];
            ulonglong2 B0 = bp[0], B1 = bp[1];
            unsigned long long a2[8] = {A0.x, A0.y, A1.x, A1.y, A2.x, A2.y, A3.x, A3.y};
            unsigned long long b2[4] = {B0.x, B0.y, B1.x, B1.y};
#pragma unroll
            for (int i = 0; i < 8; i++)
#pragma unroll
                for (int p = 0; p < 4; p++)
                    acc[i][p] = ffma2(a2[i], b2[p], acc[i][p]);
        }
        __syncthreads();
    }

#pragma unroll
    for (int i = 0; i < 8; i++) {
        int m = m0 + ty * 8 + i;
        float2* outp = (float2*)(g_pre + (size_t)m * NCOL + tx * 8);
#pragma unroll
        for (int p = 0; p < 4; p++) {
            float lo, hi;
            upk2(acc[i][p], lo, hi);
            lo += g_biasc[tx * 8 + 2 * p];
            hi += g_biasc[tx * 8 + 2 * p + 1];
            outp[p] = make_float2(lo, hi);
        }
    }
}

// ---------------- Phase 2: sequential recurrence ----------------
__device__ __forceinline__ float softplus_clip(float x) {
    float sp = fmaxf(x, 0.f) + log1pf(expf(-fabsf(x)));
    return fminf(fmaxf(sp, 1e-6f), 100.f);
}
__device__ __forceinline__ float sigm(float x) { return 1.f / (1.f + expf(-x)); }

// One block per batch element; 128 threads. Thread j<120 owns gate j (Whh row in regs).
// All threads redundantly compute a/b/z (avoids an extra barrier + broadcast).
__global__ __launch_bounds__(128) void seq_kernel(const float* __restrict__ u,
                                                  const float* __restrict__ Wih,
                                                  const float* __restrict__ Whh,
                                                  const float* __restrict__ Wa,
                                                  const float* __restrict__ Wb,
                                                  float* __restrict__ out) {
    const int b = blockIdx.x, tid = threadIdx.x;
    __shared__ float hx_s[32];
    __shared__ float gates_s[NG];

    float whh[HID], waH[HID], wbH[HID];
#pragma unroll
    for (int k = 0; k < HID; k++) { waH[k] = Wa[DENC + k]; wbH[k] = Wb[DENC + k]; }
    float wihD = 0.f;
    if (tid < NG) {
        wihD = Wih[tid * (DENC + 1) + DENC];
#pragma unroll
        for (int k = 0; k < HID; k++) whh[k] = Whh[tid * HID + k];
    } else {
#pragma unroll
        for (int k = 0; k < HID; k++) whh[k] = 0.f;
    }
    if (tid < 32) hx_s[tid] = 0.f;
    float creg = 0.f;
    __syncthreads();

    const float* prow = g_pre + (size_t)b * T_STEPS * NCOL;
    const float* urow = u + b * T_STEPS;
    const int jj = (tid < NG) ? tid : 0;

    // software-pipelined row loads (hide L2 latency across the step body)
    float xg_c = prow[jj], xa_c = prow[NG], xb_c = prow[NG + 1], u_c = urow[0];

    for (int t = 0; t < T_STEPS; t++) {
        float xg_n = 0.f, xa_n = 0.f, xb_n = 0.f, u_n = 0.f;
        if (t + 1 < T_STEPS) {
            const float* pn = prow + (t + 1) * NCOL;
            xg_n = pn[jj]; xa_n = pn[NG]; xb_n = pn[NG + 1]; u_n = urow[t + 1];
        }

        float gd = xg_c, al = xa_c, bl = xb_c;
#pragma unroll
        for (int k = 0; k < HID; k++) {
            float h = hx_s[k];                 // broadcast LDS
            gd = fmaf(h, whh[k], gd);
            al = fmaf(h, waH[k], al);
            bl = fmaf(h, wbH[k], bl);
        }

        float av = softplus_clip(al);
        float bv = softplus_clip(bl);
        float uu = fminf(fmaxf(u_c, 1e-5f), 1.f - 1e-5f);
        float p  = expf(log1pf(-uu) / bv);     // (1-u)^(1/b)
        float t1 = 1.f - p;
        float s  = expf(logf(t1) / av);        // (...)^(1/a); t1==0 -> log=-inf -> s=0 (matches ref)
        float zt = fminf(fmaxf(fmaf(s, 1.2f, -0.1f), 0.f), 1.f);

        if (tid == 0) out[b * T_STEPS + t] = zt;
        if (tid < NG) gates_s[tid] = fmaf(zt, wihD, gd);
        __syncthreads();

        if (tid < HID) {
            float ig = gates_s[tid];
            float fg = gates_s[HID + tid];
            float gg = gates_s[2 * HID + tid];
            float og = gates_s[3 * HID + tid];
            float c  = sigm(fg) * creg + sigm(ig) * tanhf(gg);
            creg = c;
            hx_s[tid] = sigm(og) * tanhf(c);
        }
        __syncthreads();

        xg_c = xg_n; xa_c = xa_n; xb_c = xb_n; u_c = u_n;
    }
}

// ---------------- launch ----------------
extern "C" void kernel_launch(void* const* d_in, const int* in_sizes, int n_in,
                              void* d_out, int out_size) {
    const float* x   = (const float*)d_in[0];
    const float* u   = (const float*)d_in[1];
    const float* Wih = (const float*)d_in[2];
    const float* Whh = (const float*)d_in[3];
    const float* bih = (const float*)d_in[4];
    const float* bhh = (const float*)d_in[5];
    const float* Wa  = (const float*)d_in[6];
    const float* ba  = (const float*)d_in[7];
    const float* Wb  = (const float*)d_in[8];
    const float* bb  = (const float*)d_in[9];
    float* out = (float*)d_out;

    pack_kernel<<<(DENC * NCOL + 255) / 256, 256>>>(Wih, Wa, Wb, bih, bhh, ba, bb);
    gemm_kernel<<<MROWS / 128, 256>>>(x);
    seq_kernel<<<BATCH, 128>>>(u, Wih, Whh, Wa, Wb, out);
}

// round 3
// speedup vs baseline: 1.4537x; 1.4537x over previous
#include <cuda_runtime.h>
#include <cuda_bf16.h>
#include <cstdint>
#include <math.h>

#define T_STEPS 512
#define BATCH   64
#define DENC    1536
#define HID     30
#define NG      120
#define NCOL    128
#define MROWS   (BATCH * T_STEPS)
#define KCH     64
#define NCHUNK  (DENC / KCH)      // 24

// ---------------- device scratch ----------------
__device__ float          g_pre[(size_t)MROWS * NCOL];   // raw preacts (no bias)
__device__ __nv_bfloat16  g_Bhi[NCOL * DENC];            // W[n][k] hi, k-major rows
__device__ __nv_bfloat16  g_Blo[NCOL * DENC];            // W[n][k] lo

// ---------------- helpers ----------------
__device__ __forceinline__ uint32_t smem_u32(const void* p) {
    uint32_t a;
    asm("{ .reg .u64 t; cvta.to.shared.u64 t, %1; cvt.u32.u64 %0, t; }" : "=r"(a) : "l"(p));
    return a;
}
__device__ __forceinline__ uint32_t swz(uint32_t off) { return off ^ ((off >> 3) & 0x70); }

__device__ __forceinline__ void cp16(uint32_t dst, const void* src) {
    asm volatile("cp.async.cg.shared.global [%0], [%1], 16;" :: "r"(dst), "l"(src));
}
__device__ __forceinline__ void cp_commit() { asm volatile("cp.async.commit_group;"); }
template <int N> __device__ __forceinline__ void cp_wait() {
    asm volatile("cp.async.wait_group %0;" :: "n"(N));
}

__device__ __forceinline__ void ldsm4(uint32_t& r0, uint32_t& r1, uint32_t& r2, uint32_t& r3,
                                      uint32_t addr) {
    asm volatile("ldmatrix.sync.aligned.m8n8.x4.shared.b16 {%0,%1,%2,%3}, [%4];"
                 : "=r"(r0), "=r"(r1), "=r"(r2), "=r"(r3) : "r"(addr));
}
__device__ __forceinline__ void mma16816(float* c, const uint32_t* a, const uint32_t* b) {
    asm volatile(
        "mma.sync.aligned.m16n8k16.row.col.f32.bf16.bf16.f32 "
        "{%0,%1,%2,%3}, {%4,%5,%6,%7}, {%8,%9}, {%0,%1,%2,%3};"
        : "+f"(c[0]), "+f"(c[1]), "+f"(c[2]), "+f"(c[3])
        : "r"(a[0]), "r"(a[1]), "r"(a[2]), "r"(a[3]), "r"(b[0]), "r"(b[1]));
}

// ---------------- Phase 0: pack W -> bf16 hi/lo [128][1536] ----------------
__global__ void pack_kernel(const float* __restrict__ Wih, const float* __restrict__ Wa,
                            const float* __restrict__ Wb) {
    int idx = blockIdx.x * blockDim.x + threadIdx.x;
    if (idx >= NCOL * DENC) return;
    int n = idx / DENC, k = idx % DENC;
    float v = 0.f;
    if (n < NG)           v = Wih[n * (DENC + 1) + k];
    else if (n == NG)     v = Wa[k];
    else if (n == NG + 1) v = Wb[k];
    __nv_bfloat16 hi = __float2bfloat16_rn(v);
    float r = v - __bfloat162float(hi);
    g_Bhi[idx] = hi;
    g_Blo[idx] = __float2bfloat16_rn(r);
}

// ---------------- Phase 1: HMMA GEMM  pre[m][n] = x[m,:] @ W[n,:] ----------------
// smem: A_hi 16K | A_lo 16K | stage0 (Bhi 16K | Blo 16K) | stage1 (...)
#define SMEM_DYN (1024 + 96 * 1024)

__global__ __launch_bounds__(256, 1) void gemm_kernel(const float* __restrict__ X) {
    extern __shared__ char dsm[];
    const uint32_t raw = smem_u32(dsm);
    const uint32_t base = (raw + 1023) & ~1023u;
    char* smb = dsm + (base - raw);
    const uint32_t AHI = base;
    const uint32_t ALO = base + 16384;
    const uint32_t BQ  = base + 32768;   // + s*32768 ; hi at +0, lo at +16384

    const int tid = threadIdx.x, lane = tid & 31, wid = tid >> 5;
    const int warp_m = wid & 3, warp_n = wid >> 2;
    const int m0 = blockIdx.x * 128;

    float acc[2][8][4];
#pragma unroll
    for (int mi = 0; mi < 2; mi++)
#pragma unroll
        for (int ni = 0; ni < 8; ni++)
#pragma unroll
            for (int q = 0; q < 4; q++) acc[mi][ni][q] = 0.f;

    // ---- B issue: 1024 16B chunks per (hi|lo); 4 each per thread ----
    auto issueB = [&](int s, int k0) {
        uint32_t bs = BQ + s * 32768;
#pragma unroll
        for (int j = 0; j < 4; j++) {
            int u = tid + j * 256;
            int row = u >> 3, c = u & 7;
            uint32_t d = swz((uint32_t)(row * 128 + c * 16));
            size_t go = (size_t)row * DENC + k0 + c * 8;
            cp16(bs + d, g_Bhi + go);
            cp16(bs + 16384 + d, g_Blo + go);
        }
        cp_commit();
    };

    // ---- X load/convert mapping: row = tid/2, 32 cols per thread ----
    const int xrow = tid >> 1, xcb = (tid & 1) * 32;
    const float* Xrow = X + (size_t)(m0 + xrow) * DENC + xcb;
    uint32_t soff[8];
#pragma unroll
    for (int j = 0; j < 8; j++)
        soff[j] = swz((uint32_t)(xrow * 128 + (xcb + 4 * j) * 2)) - (AHI - base);

    float4 xr[8];
    auto loadX = [&](int k0) {
#pragma unroll
        for (int j = 0; j < 8; j++) xr[j] = *(const float4*)(Xrow + k0 + 4 * j);
    };
    auto stsA = [&]() {
#pragma unroll
        for (int j = 0; j < 8; j++) {
            float4 v = xr[j];
            uint32_t hp0, hp1, lp0, lp1;
            asm("cvt.rn.bf16x2.f32 %0, %1, %2;" : "=r"(hp0) : "f"(v.y), "f"(v.x));
            asm("cvt.rn.bf16x2.f32 %0, %1, %2;" : "=r"(hp1) : "f"(v.w), "f"(v.z));
            float h0 = __uint_as_float(hp0 << 16);
            float h1 = __uint_as_float(hp0 & 0xffff0000u);
            float h2 = __uint_as_float(hp1 << 16);
            float h3 = __uint_as_float(hp1 & 0xffff0000u);
            asm("cvt.rn.bf16x2.f32 %0, %1, %2;" : "=r"(lp0) : "f"(v.y - h1), "f"(v.x - h0));
            asm("cvt.rn.bf16x2.f32 %0, %1, %2;" : "=r"(lp1) : "f"(v.w - h3), "f"(v.z - h2));
            *(uint2*)(smb + soff[j])         = make_uint2(hp0, hp1);
            *(uint2*)(smb + 16384 + soff[j]) = make_uint2(lp0, lp1);
        }
    };

    // ---- ldmatrix address components ----
    const int a_row = warp_m * 32 + ((lane >> 3) & 1) * 8 + (lane & 7);
    const int a_kb  = (lane >> 4) * 16;
    const int b_row = warp_n * 64 + ((lane >> 4) & 1) * 8 + (lane & 7);
    const int b_kb  = ((lane >> 3) & 1) * 16;

    issueB(0, 0);
    issueB(1, KCH);
    loadX(0);

    for (int i = 0; i < NCHUNK; i++) {
        const int s = i & 1;
        stsA();
        if (i + 1 < NCHUNK) cp_wait<1>(); else cp_wait<0>();
        __syncthreads();
        if (i + 1 < NCHUNK) loadX((i + 1) * KCH);

        const uint32_t bs = BQ + s * 32768;
#pragma unroll
        for (int k = 0; k < 4; k++) {
            const int kbyte = k * 32;
            uint32_t ah[2][4], al[2][4];
#pragma unroll
            for (int mi = 0; mi < 2; mi++) {
                uint32_t ao = swz((uint32_t)((a_row + mi * 16) * 128 + a_kb + kbyte));
                ldsm4(ah[mi][0], ah[mi][1], ah[mi][2], ah[mi][3], AHI + ao);
                ldsm4(al[mi][0], al[mi][1], al[mi][2], al[mi][3], ALO + ao);
            }
            uint32_t bh[8][2], bl[8][2];
#pragma unroll
            for (int n2 = 0; n2 < 4; n2++) {
                uint32_t bo = swz((uint32_t)((b_row + n2 * 16) * 128 + b_kb + kbyte));
                ldsm4(bh[2 * n2][0], bh[2 * n2][1], bh[2 * n2 + 1][0], bh[2 * n2 + 1][1],
                      bs + bo);
                ldsm4(bl[2 * n2][0], bl[2 * n2][1], bl[2 * n2 + 1][0], bl[2 * n2 + 1][1],
                      bs + 16384 + bo);
            }
#pragma unroll
            for (int mi = 0; mi < 2; mi++)
#pragma unroll
                for (int ni = 0; ni < 8; ni++) {
                    mma16816(acc[mi][ni], ah[mi], bh[ni]);
                    mma16816(acc[mi][ni], ah[mi], bl[ni]);
                    mma16816(acc[mi][ni], al[mi], bh[ni]);
                }
        }
        __syncthreads();
        if (i + 2 < NCHUNK) issueB(s, (i + 2) * KCH);
    }

    // ---- epilogue ----
    const int erow = m0 + warp_m * 32 + (lane >> 2);
    const int ecol = warp_n * 64 + (lane & 3) * 2;
#pragma unroll
    for (int mi = 0; mi < 2; mi++)
#pragma unroll
        for (int ni = 0; ni < 8; ni++) {
            float* p = g_pre + (size_t)(erow + mi * 16) * NCOL + ecol + ni * 8;
            *(float2*)p              = make_float2(acc[mi][ni][0], acc[mi][ni][1]);
            *(float2*)(p + 8 * NCOL) = make_float2(acc[mi][ni][2], acc[mi][ni][3]);
        }
}

// ---------------- Phase 2: sequential recurrence ----------------
__device__ __forceinline__ float ex2a(float x) { float y; asm("ex2.approx.f32 %0,%1;" : "=f"(y) : "f"(x)); return y; }
__device__ __forceinline__ float lg2a(float x) { float y; asm("lg2.approx.f32 %0,%1;" : "=f"(y) : "f"(x)); return y; }
__device__ __forceinline__ float tanha(float x) { float y; asm("tanh.approx.f32 %0,%1;" : "=f"(y) : "f"(x)); return y; }
__device__ __forceinline__ float sigm_f(float x) { return fmaf(tanha(0.5f * x), 0.5f, 0.5f); }
__device__ __forceinline__ float sp_clip(float x) {
    const float LOG2E = 1.4426950408889634f, LN2 = 0.6931471805599453f;
    float e = ex2a(-fabsf(x) * LOG2E);
    float sp = fmaxf(x, 0.f) + lg2a(1.f + e) * LN2;
    return fminf(fmaxf(sp, 1e-6f), 100.f);
}

__global__ __launch_bounds__(160) void seq_kernel(const float* __restrict__ u,
                                                  const float* __restrict__ Wih,
                                                  const float* __restrict__ Whh,
                                                  const float* __restrict__ bih,
                                                  const float* __restrict__ bhh,
                                                  const float* __restrict__ Wa,
                                                  const float* __restrict__ ba,
                                                  const float* __restrict__ Wb,
                                                  const float* __restrict__ bb,
                                                  float* __restrict__ out) {
    const int b = blockIdx.x, tid = threadIdx.x;
    __shared__ float hx_s[32];
    __shared__ float gates_s[NG];
    __shared__ float z_s;

    float whh[HID];
    float gbias = 0.f;
    float wz0 = 0.f, wz1 = 0.f, wz2 = 0.f, wz3 = 0.f;
    float waH[HID], wbH[HID];
    float abias = 0.f, bbias = 0.f;

    if (tid < NG) {
        gbias = bih[tid] + bhh[tid];
#pragma unroll
        for (int k = 0; k < HID; k++) whh[k] = Whh[tid * HID + k];
    }
    if (tid < HID) {
        wz0 = Wih[(tid)      * (DENC + 1) + DENC];
        wz1 = Wih[(tid + 30) * (DENC + 1) + DENC];
        wz2 = Wih[(tid + 60) * (DENC + 1) + DENC];
        wz3 = Wih[(tid + 90) * (DENC + 1) + DENC];
    }
    if (tid >= 128) {
#pragma unroll
        for (int k = 0; k < HID; k++) { waH[k] = Wa[DENC + k]; wbH[k] = Wb[DENC + k]; }
        abias = ba[0]; bbias = bb[0];
    }
    if (tid < 32) hx_s[tid] = 0.f;
    float creg = 0.f;
    __syncthreads();

    const float* prow = g_pre + (size_t)b * T_STEPS * NCOL;
    const float* urow = u + b * T_STEPS;

    float xg_c = (tid < NG) ? prow[tid] : 0.f;
    float xa_c = 0.f, xb_c = 0.f, u_c = 0.f;
    if (tid >= 128) { xa_c = prow[NG]; xb_c = prow[NG + 1]; u_c = urow[0]; }

    for (int t = 0; t < T_STEPS; t++) {
        float xg_n = 0.f, xa_n = 0.f, xb_n = 0.f, u_n = 0.f;
        if (t + 1 < T_STEPS) {
            const float* pn = prow + (t + 1) * NCOL;
            if (tid < NG) xg_n = pn[tid];
            if (tid >= 128) { xa_n = pn[NG]; xb_n = pn[NG + 1]; u_n = urow[t + 1]; }
        }

        if (tid < NG) {
            float gd = xg_c + gbias;
#pragma unroll
            for (int k = 0; k < HID; k++) gd = fmaf(hx_s[k], whh[k], gd);
            gates_s[tid] = gd;
        }
        if (tid >= 128) {
            float sa[4] = {0.f, 0.f, 0.f, 0.f}, sb[4] = {0.f, 0.f, 0.f, 0.f};
#pragma unroll
            for (int k = 0; k < HID; k++) {
                float h = hx_s[k];
                sa[k & 3] = fmaf(h, waH[k], sa[k & 3]);
                sb[k & 3] = fmaf(h, wbH[k], sb[k & 3]);
            }
            float al = xa_c + abias + ((sa[0] + sa[1]) + (sa[2] + sa[3]));
            float bl = xb_c + bbias + ((sb[0] + sb[1]) + (sb[2] + sb[3]));
            float av = sp_clip(al), bv = sp_clip(bl);
            float uu = fminf(fmaxf(u_c, 1e-5f), 1.f - 1e-5f);
            float p  = ex2a(lg2a(1.f - uu) * __fdividef(1.f, bv));
            float s  = ex2a(lg2a(1.f - p)  * __fdividef(1.f, av));
            float zt = fminf(fmaxf(fmaf(s, 1.2f, -0.1f), 0.f), 1.f);
            if (tid == 128) { z_s = zt; out[b * T_STEPS + t] = zt; }
        }
        __syncthreads();

        if (tid < HID) {
            float z  = z_s;
            float gi = gates_s[tid]      + z * wz0;
            float gf = gates_s[30 + tid] + z * wz1;
            float gg = gates_s[60 + tid] + z * wz2;
            float go = gates_s[90 + tid] + z * wz3;
            float c  = sigm_f(gf) * creg + sigm_f(gi) * tanha(gg);
            creg = c;
            hx_s[tid] = sigm_f(go) * tanha(c);
        }
        __syncthreads();

        xg_c = xg_n; xa_c = xa_n; xb_c = xb_n; u_c = u_n;
    }
}

// ---------------- launch ----------------
extern "C" void kernel_launch(void* const* d_in, const int* in_sizes, int n_in,
                              void* d_out, int out_size) {
    const float* x   = (const float*)d_in[0];
    const float* u   = (const float*)d_in[1];
    const float* Wih = (const float*)d_in[2];
    const float* Whh = (const float*)d_in[3];
    const float* bih = (const float*)d_in[4];
    const float* bhh = (const float*)d_in[5];
    const float* Wa  = (const float*)d_in[6];
    const float* ba  = (const float*)d_in[7];
    const float* Wb  = (const float*)d_in[8];
    const float* bb  = (const float*)d_in[9];
    float* out = (float*)d_out;

    cudaFuncSetAttribute(gemm_kernel, cudaFuncAttributeMaxDynamicSharedMemorySize, SMEM_DYN);

    pack_kernel<<<(NCOL * DENC + 255) / 256, 256>>>(Wih, Wa, Wb);
    gemm_kernel<<<MROWS / 128, 256, SMEM_DYN>>>(x);
    seq_kernel<<<BATCH, 160>>>(u, Wih, Whh, bih, bhh, Wa, ba, Wb, bb, out);
}